// round 9
// baseline (speedup 1.0000x reference)
#include <cuda_runtime.h>
#include <cuda_bf16.h>
#include <cstdint>
#include <math.h>

#define N_ROWS 4096
#define DIMS   128
#define NJ     4
#define TOPK   16
#define CT     64          // candidates per tile
#define NITER  (N_ROWS / CT)
#define BUFCAP 112
#define SEL_TRIG 48        // select when cnt exceeds this (48 + 64 <= 112)

// smem map (bytes)
#define SM_AHI   0
#define SM_ALO   32768
#define SM_B     65536      // two stages of (hi 16K + lo 16K)
#define SM_EXCH  131072     // 8 warps x 16 x 68 uints = 34816
#define SM_BUF   165888     // 8 warps x 16 x 112 uints = 57344
#define SM_TGT   223232     // 4096 bytes
#define SM_TOTAL 227328

// ---------------- device scratch (static, allocation-free) ----------------
__device__ __nv_bfloat16 g_fhi[N_ROWS * DIMS];
__device__ __nv_bfloat16 g_flo[N_ROWS * DIMS];
__device__ __nv_bfloat16 g_nhi[(size_t)NJ * N_ROWS * DIMS];
__device__ __nv_bfloat16 g_nlo[(size_t)NJ * N_ROWS * DIMS];
__device__ float g_topbuf[N_ROWS * NJ * TOPK];
__device__ float g_part[32];

// ---------------- PTX helpers (base-arch portable) ----------------
__device__ __forceinline__ uint32_t smem_u32(const void* p) {
    uint32_t a;
    asm("{ .reg .u64 t; cvta.to.shared.u64 t, %1; cvt.u32.u64 %0, t; }" : "=r"(a) : "l"(p));
    return a;
}
__device__ __forceinline__ void ldsm4(uint32_t* r, uint32_t a) {
    asm volatile("ldmatrix.sync.aligned.m8n8.x4.shared.b16 {%0,%1,%2,%3}, [%4];"
                 : "=r"(r[0]), "=r"(r[1]), "=r"(r[2]), "=r"(r[3]) : "r"(a));
}
__device__ __forceinline__ void mma16816(float* c, const uint32_t* a,
                                         uint32_t b0, uint32_t b1) {
    asm volatile(
        "mma.sync.aligned.m16n8k16.row.col.f32.bf16.bf16.f32 "
        "{%0,%1,%2,%3}, {%4,%5,%6,%7}, {%8,%9}, {%0,%1,%2,%3};"
        : "+f"(c[0]), "+f"(c[1]), "+f"(c[2]), "+f"(c[3])
        : "r"(a[0]), "r"(a[1]), "r"(a[2]), "r"(a[3]), "r"(b0), "r"(b1));
}

// byte offset in a (nr8*8)x128 bf16 tile: 8-row x 128B atoms + XOR swizzle
__device__ __forceinline__ uint32_t toffs(int row, int col, int nr8) {
    return (uint32_t)(((row >> 3) + (col >> 6) * nr8) * 1024 + (row & 7) * 128 +
                      ((((col >> 3) & 7) ^ (row & 7)) * 16));
}
__device__ __forceinline__ void cpa16(uint32_t dst, const void* src) {
    asm volatile("cp.async.cg.shared.global [%0], [%1], 16;" :: "r"(dst), "l"(src));
}

// float <-> order-preserving uint
__device__ __forceinline__ uint32_t fsort(float f) {
    uint32_t u = __float_as_uint(f);
    return ((int)u < 0) ? ~u : (u | 0x80000000u);
}
__device__ __forceinline__ float usort_back(uint32_t u) {
    return (u & 0x80000000u) ? __uint_as_float(u & 0x7fffffffu) : __uint_as_float(~u);
}

// ---------------- kernel 0: normalize + bf16 hi/lo split ----------------
__global__ void convert_kernel(const float* __restrict__ feat,
                               const float* __restrict__ negs) {
    int gw = (blockIdx.x * blockDim.x + threadIdx.x) >> 5;
    int lane = threadIdx.x & 31;
    if (gw >= N_ROWS + NJ * N_ROWS) return;
    const float* src;
    __nv_bfloat16 *dh, *dl;
    if (gw < N_ROWS) {
        src = feat + (size_t)gw * DIMS;
        dh = g_fhi + (size_t)gw * DIMS;
        dl = g_flo + (size_t)gw * DIMS;
    } else {
        int r = gw - N_ROWS;
        src = negs + (size_t)r * DIMS;
        dh = g_nhi + (size_t)r * DIMS;
        dl = g_nlo + (size_t)r * DIMS;
    }
    float4 v = ((const float4*)src)[lane];
    float s = v.x * v.x + v.y * v.y + v.z * v.z + v.w * v.w;
#pragma unroll
    for (int off = 16; off; off >>= 1) s += __shfl_xor_sync(0xffffffffu, s, off);
    float rinv = 1.0f / fmaxf(sqrtf(s), 1e-12f);
    float x[4] = {v.x * rinv, v.y * rinv, v.z * rinv, v.w * rinv};
    __nv_bfloat16 h[4], l[4];
#pragma unroll
    for (int e = 0; e < 4; e++) {
        h[e] = __float2bfloat16(x[e]);
        l[e] = __float2bfloat16(x[e] - __bfloat162float(h[e]));
    }
    __nv_bfloat162* dh2 = (__nv_bfloat162*)(dh + 4 * lane);
    __nv_bfloat162* dl2 = (__nv_bfloat162*)(dl + 4 * lane);
    dh2[0] = __nv_bfloat162{h[0], h[1]};
    dh2[1] = __nv_bfloat162{h[2], h[3]};
    dl2[0] = __nv_bfloat162{l[0], l[1]};
    dl2[1] = __nv_bfloat162{l[2], l[3]};
}

// ---------------- warp-collective exact top-16 (sortable-uint domain) ----------------
// Selects the 16 largest of bq[0..cnt) (cnt<=112), compacts them (desc) to
// bq[0..16), optionally writes floats to outp. Returns the 16th largest.
__device__ __noinline__ uint32_t select16u(uint32_t* bq, int cnt, int lane,
                                           float* outp) {
    uint32_t x0 = (lane < cnt)      ? bq[lane]      : 0u;
    uint32_t x1 = (lane + 32 < cnt) ? bq[lane + 32] : 0u;
    uint32_t x2 = (lane + 64 < cnt) ? bq[lane + 64] : 0u;
    uint32_t x3 = (lane + 96 < cnt) ? bq[lane + 96] : 0u;
    uint32_t wm = 0;
#pragma unroll 1
    for (int k = 0; k < TOPK; k++) {
        uint32_t lm = max(max(x0, x1), max(x2, x3));
        wm = __reduce_max_sync(0xffffffffu, lm);
        unsigned b = __ballot_sync(0xffffffffu, lm == wm);
        if (lane == __ffs(b) - 1) {
            if      (x0 == wm) x0 = 0u;
            else if (x1 == wm) x1 = 0u;
            else if (x2 == wm) x2 = 0u;
            else               x3 = 0u;
        }
        if (lane == 0) {
            bq[k] = wm;
            if (outp) outp[k] = usort_back(wm);
        }
    }
    __syncwarp();
    return wm;
}

// ---------------- kernel 1: fused HMMA GEMM + per-query top-16 ----------------
// grid (32 queryTiles, NJ), block 256. Warp w owns queries [w*16, w*16+16).
__global__ void __launch_bounds__(256, 1)
gemm_topk_kernel(const int* __restrict__ target, const int* __restrict__ idxp) {
    extern __shared__ char smem[];
    const int t = threadIdx.x, wid = t >> 5, lane = t & 31;
    const int n0 = blockIdx.x * 128;
    const int j  = blockIdx.y;
    const uint32_t sb = smem_u32(smem);
    const bool maskj = (j == *idxp);

    const __nv_bfloat16* nh = g_nhi + (size_t)j * N_ROWS * DIMS;
    const __nv_bfloat16* nl = g_nlo + (size_t)j * N_ROWS * DIMS;

    // target bytes -> smem (classes fit in 8 bits)
    uint8_t* tgt8 = (uint8_t*)(smem + SM_TGT);
    for (int i = t; i < N_ROWS; i += 256) tgt8[i] = (uint8_t)target[i];

    // prologue: A (128q x 128d, hi+lo) + B stage 0 (64c x 128d, hi+lo)
#pragma unroll
    for (int i = 0; i < 8; i++) {
        int id = t + 256 * i, row = id >> 4, kch = id & 15;
        uint32_t o = toffs(row, kch * 8, 16);
        cpa16(sb + SM_AHI + o, g_fhi + (size_t)(n0 + row) * DIMS + kch * 8);
        cpa16(sb + SM_ALO + o, g_flo + (size_t)(n0 + row) * DIMS + kch * 8);
    }
#pragma unroll
    for (int i = 0; i < 4; i++) {
        int id = t + 256 * i, row = id >> 4, kch = id & 15;
        uint32_t o = toffs(row, kch * 8, 8);
        cpa16(sb + SM_B + o,         nh + (size_t)row * DIMS + kch * 8);
        cpa16(sb + SM_B + 16384 + o, nl + (size_t)row * DIMS + kch * 8);
    }
    asm volatile("cp.async.commit_group;");

    const uint32_t um = fsort(-1e9f);                 // mask fill value
    uint32_t* exch_w = (uint32_t*)(smem + SM_EXCH) + wid * 16 * 68;
    uint32_t* buf_w  = (uint32_t*)(smem + SM_BUF)  + wid * 16 * BUFCAP;
    const unsigned lmask = (1u << lane) - 1u;

    // ldmatrix lane-address pattern (matches verified R8 layout)
    const int a_r  = ((lane >> 3) & 1) * 8 + (lane & 7);
    const int a_c8 = (lane >> 4) * 8;
    const int qb   = wid * 16;
    const int tq0  = tgt8[n0 + qb + (lane >> 2)];       // filled below barrier-safe:
    // (tgt8 written above by all threads; first real use is after the first
    //  __syncthreads inside the loop — reload there instead to be safe)

    uint32_t tau[16];
    int      cnt[16];
#pragma unroll
    for (int q = 0; q < 16; q++) { tau[q] = 0u; cnt[q] = 0; }

#pragma unroll 1
    for (int it = 0; it < NITER; ++it) {
        const int cur = it & 1, nxt = cur ^ 1;
        if (it < NITER - 1) {
            const size_t m1 = (size_t)(it + 1) * CT;
#pragma unroll
            for (int i = 0; i < 4; i++) {
                int id = t + 256 * i, row = id >> 4, kch = id & 15;
                uint32_t o = toffs(row, kch * 8, 8) + (uint32_t)nxt * 32768u;
                cpa16(sb + SM_B + o,         nh + (m1 + row) * DIMS + kch * 8);
                cpa16(sb + SM_B + 16384 + o, nl + (m1 + row) * DIMS + kch * 8);
            }
            asm volatile("cp.async.commit_group;");
            asm volatile("cp.async.wait_group 1;");
        } else {
            asm volatile("cp.async.wait_group 0;");
        }
        __syncthreads();

        const uint32_t bh_base = sb + SM_B + (uint32_t)cur * 32768u;
        const uint32_t bl_base = bh_base + 16384u;

        float c[8][4];
#pragma unroll
        for (int ni = 0; ni < 8; ni++)
#pragma unroll
            for (int e = 0; e < 4; e++) c[ni][e] = 0.f;

#pragma unroll
        for (int kc = 0; kc < 8; ++kc) {
            uint32_t ah[4], al[4];
            uint32_t offA = toffs(qb + a_r, kc * 16 + a_c8, 16);
            ldsm4(ah, sb + SM_AHI + offA);
            ldsm4(al, sb + SM_ALO + offA);
#pragma unroll
            for (int g = 0; g < 4; g++) {
                uint32_t bh[4], bl[4];
                uint32_t offB = toffs(g * 16 + a_r, kc * 16 + a_c8, 8);
                ldsm4(bh, bh_base + offB);
                ldsm4(bl, bl_base + offB);
                // frag n(g*16+0..7) = {r0,r2}; n(g*16+8..15) = {r1,r3}
                mma16816(c[2 * g],     ah, bh[0], bh[2]);
                mma16816(c[2 * g],     ah, bl[0], bl[2]);
                mma16816(c[2 * g],     al, bh[0], bh[2]);
                mma16816(c[2 * g + 1], ah, bh[1], bh[3]);
                mma16816(c[2 * g + 1], ah, bl[1], bl[3]);
                mma16816(c[2 * g + 1], al, bh[1], bh[3]);
            }
        }
        __syncthreads();   // tile reads done before next prefetch overwrites

        // --- epilogue: mask + sortable-uint convert -> warp-private exchange ---
        const int m0 = it * CT;
        const int q0 = lane >> 2;
        const int ta = tgt8[n0 + qb + q0];
        const int tb = tgt8[n0 + qb + q0 + 8];
#pragma unroll
        for (int ni = 0; ni < 8; ni++) {
            const int col = ni * 8 + (lane & 3) * 2;
            unsigned short tc2 = *(const unsigned short*)(tgt8 + m0 + col);
            const int tc0 = tc2 & 0xff, tc1 = tc2 >> 8;
            uint2 v0, v1;
            v0.x = (maskj && tc0 == ta) ? um : fsort(c[ni][0]);
            v0.y = (maskj && tc1 == ta) ? um : fsort(c[ni][1]);
            v1.x = (maskj && tc0 == tb) ? um : fsort(c[ni][2]);
            v1.y = (maskj && tc1 == tb) ? um : fsort(c[ni][3]);
            *(uint2*)(exch_w + q0 * 68 + col)       = v0;
            *(uint2*)(exch_w + (q0 + 8) * 68 + col) = v1;
        }
        __syncwarp();

        // --- merge: threshold filter + ballot-compacted append ---
#pragma unroll
        for (int q = 0; q < 16; q++) {
            uint2 e = *(const uint2*)(exch_w + q * 68 + lane * 2);
            bool p0 = e.x > tau[q], p1 = e.y > tau[q];
            unsigned b0 = __ballot_sync(0xffffffffu, p0);
            unsigned b1 = __ballot_sync(0xffffffffu, p1);
            if (b0 | b1) {
                int base = cnt[q];
                if (p0) buf_w[q * BUFCAP + base + __popc(b0 & lmask)] = e.x;
                int base1 = base + __popc(b0);
                if (p1) buf_w[q * BUFCAP + base1 + __popc(b1 & lmask)] = e.y;
                cnt[q] = base1 + __popc(b1);
                __syncwarp();
                if (cnt[q] > SEL_TRIG) {
                    tau[q] = select16u(buf_w + q * BUFCAP, cnt[q], lane, nullptr);
                    cnt[q] = TOPK;
                }
            }
        }
        __syncwarp();
    }

    // --- final exact top-16 per query -> g_topbuf (descending floats) ---
#pragma unroll 1
    for (int q = 0; q < 16; q++) {
        float* outp = g_topbuf + ((size_t)(n0 + qb + q) * NJ + j) * TOPK;
        select16u(buf_w + q * BUFCAP, cnt[q], lane, outp);
    }
    (void)tq0;
}

// ---------------- kernel 2: entropy + decay, per-block partials ----------------
__global__ void entropy_kernel() {
    __shared__ float red[128];
    int n = blockIdx.x * 128 + threadIdx.x;
    const float* tb = g_topbuf + (size_t)n * (NJ * TOPK);

    float wsum = 0.f, w = 1.f;
#pragma unroll
    for (int k = 0; k < TOPK; k++) { wsum += w; w *= 0.95f; }

    float acc = 0.f; w = 1.f;
#pragma unroll
    for (int k = 0; k < TOPK; k++) {
        float l0 = tb[0 * TOPK + k] * 100.0f;
        float l1 = tb[1 * TOPK + k] * 100.0f;
        float l2 = tb[2 * TOPK + k] * 100.0f;
        float l3 = tb[3 * TOPK + k] * 100.0f;
        float m = fmaxf(fmaxf(l0, l1), fmaxf(l2, l3));
        float e0 = expf(l0 - m), e1 = expf(l1 - m), e2 = expf(l2 - m), e3 = expf(l3 - m);
        float s  = e0 + e1 + e2 + e3;
        float t1 = e0 * (l0 - m) + e1 * (l1 - m) + e2 * (l2 - m) + e3 * (l3 - m);
        float ent = t1 / s - logf(s);
        acc += ent * w;
        w *= 0.95f;
    }
    acc /= wsum;

    red[threadIdx.x] = acc;
    __syncthreads();
    for (int off = 64; off; off >>= 1) {
        if (threadIdx.x < off) red[threadIdx.x] += red[threadIdx.x + off];
        __syncthreads();
    }
    if (threadIdx.x == 0) g_part[blockIdx.x] = red[0];
}

// ---------------- kernel 3: deterministic final reduction ----------------
__global__ void final_kernel(float* out) {
    int lane = threadIdx.x;
    float v = g_part[lane];
#pragma unroll
    for (int off = 16; off; off >>= 1) v += __shfl_xor_sync(0xffffffffu, v, off);
    if (lane == 0) out[0] = v / (float)N_ROWS + logf((float)NJ);
}

// ---------------- launch ----------------
extern "C" void kernel_launch(void* const* d_in, const int* in_sizes, int n_in,
                              void* d_out, int out_size) {
    const float* feat   = (const float*)d_in[0];
    const int*   target = (const int*)d_in[1];
    const float* negs   = (const float*)d_in[2];
    const int*   idxp   = (const int*)d_in[3];
    float*       out    = (float*)d_out;

    cudaFuncSetAttribute(gemm_topk_kernel,
                         cudaFuncAttributeMaxDynamicSharedMemorySize, SM_TOTAL);

    convert_kernel<<<(N_ROWS + NJ * N_ROWS) / 8, 256>>>(feat, negs);
    gemm_topk_kernel<<<dim3(N_ROWS / 128, NJ), 256, SM_TOTAL>>>(target, idxp);
    entropy_kernel<<<32, 128>>>();
    final_kernel<<<1, 32>>>(out);
}

// round 10
// speedup vs baseline: 2.0703x; 2.0703x over previous
#include <cuda_runtime.h>
#include <cuda_bf16.h>
#include <cstdint>
#include <math.h>

#define N_ROWS 4096
#define DIMS   128
#define NJ     4
#define TOPK   16

// smem map (bytes): 6 x 32KB bf16 tiles = 192KB
#define SM_AHI  0
#define SM_ALO  32768
#define SM_BHI0 65536
#define SM_BLO0 98304
#define SM_BHI1 131072
#define SM_BLO1 163840
#define SM_TOTAL 196608

// ---------------- device scratch (static, allocation-free) ----------------
__device__ __nv_bfloat16 g_fhi[N_ROWS * DIMS];
__device__ __nv_bfloat16 g_flo[N_ROWS * DIMS];
__device__ __nv_bfloat16 g_nhi[(size_t)NJ * N_ROWS * DIMS];
__device__ __nv_bfloat16 g_nlo[(size_t)NJ * N_ROWS * DIMS];
__device__ float g_sims[(size_t)N_ROWS * N_ROWS];   // 64 MB, reused per j (L2-resident)
__device__ float g_topbuf[N_ROWS * NJ * TOPK];
__device__ float g_part[256];

// ---------------- PTX helpers (base-arch portable: no tcgen05) ----------------
__device__ __forceinline__ uint32_t smem_u32(const void* p) {
    uint32_t a;
    asm("{ .reg .u64 t; cvta.to.shared.u64 t, %1; cvt.u32.u64 %0, t; }" : "=r"(a) : "l"(p));
    return a;
}
__device__ __forceinline__ void ldsm4(uint32_t* r, uint32_t a) {
    asm volatile("ldmatrix.sync.aligned.m8n8.x4.shared.b16 {%0,%1,%2,%3}, [%4];"
                 : "=r"(r[0]), "=r"(r[1]), "=r"(r[2]), "=r"(r[3]) : "r"(a));
}
__device__ __forceinline__ void ldsm2(uint32_t* r, uint32_t a) {
    asm volatile("ldmatrix.sync.aligned.m8n8.x2.shared.b16 {%0,%1}, [%2];"
                 : "=r"(r[0]), "=r"(r[1]) : "r"(a));
}
__device__ __forceinline__ void mma16816(float* c, const uint32_t* a, const uint32_t* b) {
    asm volatile(
        "mma.sync.aligned.m16n8k16.row.col.f32.bf16.bf16.f32 "
        "{%0,%1,%2,%3}, {%4,%5,%6,%7}, {%8,%9}, {%0,%1,%2,%3};"
        : "+f"(c[0]), "+f"(c[1]), "+f"(c[2]), "+f"(c[3])
        : "r"(a[0]), "r"(a[1]), "r"(a[2]), "r"(a[3]), "r"(b[0]), "r"(b[1]));
}

// Byte offset of (row, col) in a 128x128 bf16 tile stored as 8-row x 128B
// blocked atoms with SW128 XOR swizzle. col must be a multiple of 8.
__device__ __forceinline__ uint32_t toff(int row, int col) {
    return (uint32_t)(((row >> 3) + (col >> 6) * 16) * 1024 + (row & 7) * 128 +
                      ((((col >> 3) & 7) ^ (row & 7)) * 16));
}

// Stage a 128x128 bf16 tile (row-major in gmem) into swizzled smem via cp.async.
__device__ __forceinline__ void stage_async(uint32_t sdst,
                                            const __nv_bfloat16* __restrict__ g,
                                            int t) {
#pragma unroll
    for (int i = 0; i < 8; i++) {
        int c = t + 256 * i;              // 0..2047 16B chunks
        int row = c >> 4, kch = c & 15;
        uint32_t dst = sdst + toff(row, kch * 8);
        const void* src = g + row * DIMS + kch * 8;
        asm volatile("cp.async.cg.shared.global [%0], [%1], 16;" :: "r"(dst), "l"(src));
    }
}

// ---------------- kernel 0: normalize + bf16 hi/lo split ----------------
__global__ void convert_kernel(const float* __restrict__ feat,
                               const float* __restrict__ negs) {
    int gw = (blockIdx.x * blockDim.x + threadIdx.x) >> 5;
    int lane = threadIdx.x & 31;
    if (gw >= N_ROWS + NJ * N_ROWS) return;
    const float* src;
    __nv_bfloat16 *dh, *dl;
    if (gw < N_ROWS) {
        src = feat + (size_t)gw * DIMS;
        dh = g_fhi + (size_t)gw * DIMS;
        dl = g_flo + (size_t)gw * DIMS;
    } else {
        int r = gw - N_ROWS;
        src = negs + (size_t)r * DIMS;
        dh = g_nhi + (size_t)r * DIMS;
        dl = g_nlo + (size_t)r * DIMS;
    }
    float4 v = ((const float4*)src)[lane];
    float s = v.x * v.x + v.y * v.y + v.z * v.z + v.w * v.w;
#pragma unroll
    for (int off = 16; off; off >>= 1) s += __shfl_xor_sync(0xffffffffu, s, off);
    float rinv = 1.0f / fmaxf(sqrtf(s), 1e-12f);
    float x[4] = {v.x * rinv, v.y * rinv, v.z * rinv, v.w * rinv};
    __nv_bfloat16 h[4], l[4];
#pragma unroll
    for (int e = 0; e < 4; e++) {
        h[e] = __float2bfloat16(x[e]);
        l[e] = __float2bfloat16(x[e] - __bfloat162float(h[e]));
    }
    __nv_bfloat162* dh2 = (__nv_bfloat162*)(dh + 4 * lane);
    __nv_bfloat162* dl2 = (__nv_bfloat162*)(dl + 4 * lane);
    dh2[0] = __nv_bfloat162{h[0], h[1]};
    dh2[1] = __nv_bfloat162{h[2], h[3]};
    dl2[0] = __nv_bfloat162{l[0], l[1]};
    dl2[1] = __nv_bfloat162{l[2], l[3]};
}

// ---------------- kernel 1: HMMA GEMM (bf16 hi/lo 3-term) -> g_sims (one j) ----------------
// grid (32 queryTiles, 4 candChunks), block 256 (8 warps; warp tile 64q x 32cand)
// Each CTA covers 128 queries x 1024 candidates (8 iterations of 128).
__global__ void __launch_bounds__(256, 1) gemm_kernel(int j) {
    extern __shared__ char smem[];
    const int t = threadIdx.x, wid = t >> 5, lane = t & 31;
    const int n0 = blockIdx.x * 128;
    const int c0 = blockIdx.y * 1024;
    const uint32_t sb = smem_u32(smem);

    const __nv_bfloat16* nh = g_nhi + ((size_t)j * N_ROWS + c0) * DIMS;
    const __nv_bfloat16* nl = g_nlo + ((size_t)j * N_ROWS + c0) * DIMS;

    // prologue: A (queries, fixed) + B tile 0
    stage_async(sb + SM_AHI, g_fhi + (size_t)n0 * DIMS, t);
    stage_async(sb + SM_ALO, g_flo + (size_t)n0 * DIMS, t);
    stage_async(sb + SM_BHI0, nh, t);
    stage_async(sb + SM_BLO0, nl, t);
    asm volatile("cp.async.commit_group;");

    const int qoff = (wid >> 2) * 64;
    const int coff = (wid & 3) * 32;
    const int a_r  = ((lane >> 3) & 1) * 8 + (lane & 7);
    const int a_c8 = (lane >> 4) * 8;
    const int b_r  = (lane & 7);
    const int b_c8 = ((lane >> 3) & 1) * 8;

#pragma unroll 1
    for (int it = 0; it < 8; ++it) {
        const int cur = it & 1;
        if (it < 7) {
            stage_async(sb + (cur ? SM_BHI0 : SM_BHI1), nh + (size_t)(it + 1) * 128 * DIMS, t);
            stage_async(sb + (cur ? SM_BLO0 : SM_BLO1), nl + (size_t)(it + 1) * 128 * DIMS, t);
            asm volatile("cp.async.commit_group;");
            asm volatile("cp.async.wait_group 1;");
        } else {
            asm volatile("cp.async.wait_group 0;");
        }
        __syncthreads();

        const uint32_t bh_base = sb + (cur ? SM_BHI1 : SM_BHI0);
        const uint32_t bl_base = sb + (cur ? SM_BLO1 : SM_BLO0);

        float c[4][4][4];
#pragma unroll
        for (int mi = 0; mi < 4; mi++)
#pragma unroll
            for (int ni = 0; ni < 4; ni++)
#pragma unroll
                for (int e = 0; e < 4; e++) c[mi][ni][e] = 0.f;

#pragma unroll
        for (int kc = 0; kc < 8; ++kc) {
            uint32_t ah[4][4], al[4][4], bh[4][2], bl[4][2];
#pragma unroll
            for (int mi = 0; mi < 4; mi++) {
                uint32_t off = toff(qoff + mi * 16 + a_r, kc * 16 + a_c8);
                ldsm4(ah[mi], sb + SM_AHI + off);
                ldsm4(al[mi], sb + SM_ALO + off);
            }
#pragma unroll
            for (int ni = 0; ni < 4; ni++) {
                uint32_t off = toff(coff + ni * 8 + b_r, kc * 16 + b_c8);
                ldsm2(bh[ni], bh_base + off);
                ldsm2(bl[ni], bl_base + off);
            }
#pragma unroll
            for (int mi = 0; mi < 4; mi++)
#pragma unroll
                for (int ni = 0; ni < 4; ni++) mma16816(c[mi][ni], ah[mi], bh[ni]);
#pragma unroll
            for (int mi = 0; mi < 4; mi++)
#pragma unroll
                for (int ni = 0; ni < 4; ni++) mma16816(c[mi][ni], ah[mi], bl[ni]);
#pragma unroll
            for (int mi = 0; mi < 4; mi++)
#pragma unroll
                for (int ni = 0; ni < 4; ni++) mma16816(c[mi][ni], al[mi], bh[ni]);
        }
        __syncthreads();   // smem reads done before next iter's cp.async overwrite

        // epilogue: C frag -> sims[q][cand] (coalesced STG.64)
        const int cand0 = c0 + it * 128 + coff;
#pragma unroll
        for (int mi = 0; mi < 4; mi++) {
            const int q = n0 + qoff + mi * 16 + (lane >> 2);
#pragma unroll
            for (int ni = 0; ni < 4; ni++) {
                const int cd = cand0 + ni * 8 + (lane & 3) * 2;
                *(float2*)&g_sims[(size_t)q * N_ROWS + cd] =
                    make_float2(c[mi][ni][0], c[mi][ni][1]);
                *(float2*)&g_sims[(size_t)(q + 8) * N_ROWS + cd] =
                    make_float2(c[mi][ni][2], c[mi][ni][3]);
            }
        }
    }
}

// ---------------- warp top-16 selection over a smem buffer ----------------
__device__ __forceinline__ float warp_select16(float* bw, int cnt, int lane,
                                               float* outp) {
    float x0 = (lane < cnt)      ? bw[lane]      : -INFINITY;
    float x1 = (lane + 32 < cnt) ? bw[lane + 32] : -INFINITY;
    float x2 = (lane + 64 < cnt) ? bw[lane + 64] : -INFINITY;
    float x3 = (lane + 96 < cnt) ? bw[lane + 96] : -INFINITY;
    float wm = -INFINITY;
#pragma unroll 1
    for (int k = 0; k < TOPK; k++) {
        float lm = fmaxf(fmaxf(x0, x1), fmaxf(x2, x3));
        wm = lm;
#pragma unroll
        for (int off = 16; off; off >>= 1)
            wm = fmaxf(wm, __shfl_xor_sync(0xffffffffu, wm, off));
        unsigned b = __ballot_sync(0xffffffffu, lm == wm);
        int leader = __ffs(b) - 1;
        if (lane == leader) {
            if      (x0 == wm) x0 = -INFINITY;
            else if (x1 == wm) x1 = -INFINITY;
            else if (x2 == wm) x2 = -INFINITY;
            else               x3 = -INFINITY;
        }
        if (lane == 0) {
            bw[k] = wm;
            if (outp) outp[k] = wm;
        }
    }
    return wm;
}

// ---------------- kernel 2: per-row top-16 over 4096 candidates (one j) ----------------
__global__ void __launch_bounds__(256)
topk_kernel(const int* __restrict__ target, const int* __restrict__ idxp, int j) {
    __shared__ float buf[8][128];
    const int w    = threadIdx.x >> 5;
    const int lane = threadIdx.x & 31;
    const int row  = blockIdx.x * 8 + w;
    const bool maskj = (j == *idxp);
    const int  myt   = target[row];
    const float* rowp = g_sims + (size_t)row * N_ROWS;
    float* bw = buf[w];
    const unsigned lmask = (1u << lane) - 1u;

    float tau = -INFINITY;
    int   cnt = 0;

#pragma unroll 1
    for (int it = 0; it < N_ROWS / 128; ++it) {
        int c0 = it * 128 + lane * 4;
        float4 v = *(const float4*)(rowp + c0);
        if (maskj) {
            int4 tg = *(const int4*)(target + c0);
            if (tg.x == myt) v.x = -1e9f;
            if (tg.y == myt) v.y = -1e9f;
            if (tg.z == myt) v.z = -1e9f;
            if (tg.w == myt) v.w = -1e9f;
        }
        float vv[4] = {v.x, v.y, v.z, v.w};
#pragma unroll
        for (int e = 0; e < 4; e++) {
            bool p = vv[e] > tau;
            unsigned m = __ballot_sync(0xffffffffu, p);
            if (m) {
                if (p) bw[cnt + __popc(m & lmask)] = vv[e];
                cnt += __popc(m);
                __syncwarp();
                if (cnt > 96) {
                    tau = warp_select16(bw, cnt, lane, nullptr);
                    cnt = TOPK;
                    __syncwarp();
                }
            }
        }
    }
    float* outp = g_topbuf + ((size_t)row * NJ + j) * TOPK;
    warp_select16(bw, cnt, lane, outp);
}

// ---------------- kernel 3: entropy + decay, fine-grained (one (n,k) per thread) ----------------
__global__ void entropy_kernel() {
    __shared__ float red[256];
    const int id = blockIdx.x * 256 + threadIdx.x;   // 0..65535
    const int n = id >> 4, k = id & 15;
    const float* tb = g_topbuf + (size_t)n * (NJ * TOPK);

    float wsum = 0.f, w = 1.f;
#pragma unroll
    for (int i = 0; i < TOPK; i++) { wsum += w; w *= 0.95f; }
    float wk = 1.f;
    for (int i = 0; i < 16; i++) wk = (i < k) ? wk * 0.95f : wk;

    float l0 = tb[0 * TOPK + k] * 100.0f;
    float l1 = tb[1 * TOPK + k] * 100.0f;
    float l2 = tb[2 * TOPK + k] * 100.0f;
    float l3 = tb[3 * TOPK + k] * 100.0f;
    float m = fmaxf(fmaxf(l0, l1), fmaxf(l2, l3));
    float e0 = expf(l0 - m), e1 = expf(l1 - m), e2 = expf(l2 - m), e3 = expf(l3 - m);
    float s  = e0 + e1 + e2 + e3;
    float t1 = e0 * (l0 - m) + e1 * (l1 - m) + e2 * (l2 - m) + e3 * (l3 - m);
    float ent = t1 / s - logf(s);
    float acc = ent * wk / wsum;

    red[threadIdx.x] = acc;
    __syncthreads();
    for (int off = 128; off; off >>= 1) {
        if (threadIdx.x < off) red[threadIdx.x] += red[threadIdx.x + off];
        __syncthreads();
    }
    if (threadIdx.x == 0) g_part[blockIdx.x] = red[0];
}

// ---------------- kernel 4: deterministic final reduction (256 partials) ----------------
__global__ void final_kernel(float* out) {
    __shared__ float red[256];
    red[threadIdx.x] = g_part[threadIdx.x];
    __syncthreads();
    for (int off = 128; off; off >>= 1) {
        if (threadIdx.x < off) red[threadIdx.x] += red[threadIdx.x + off];
        __syncthreads();
    }
    if (threadIdx.x == 0) out[0] = red[0] / (float)N_ROWS + logf((float)NJ);
}

// ---------------- launch ----------------
extern "C" void kernel_launch(void* const* d_in, const int* in_sizes, int n_in,
                              void* d_out, int out_size) {
    const float* feat   = (const float*)d_in[0];
    const int*   target = (const int*)d_in[1];
    const float* negs   = (const float*)d_in[2];
    const int*   idxp   = (const int*)d_in[3];
    float*       out    = (float*)d_out;

    cudaFuncSetAttribute(gemm_kernel,
                         cudaFuncAttributeMaxDynamicSharedMemorySize, SM_TOTAL);

    convert_kernel<<<(N_ROWS + NJ * N_ROWS) / 8, 256>>>(feat, negs);
    for (int j = 0; j < NJ; j++) {
        gemm_kernel<<<dim3(32, 4), 256, SM_TOTAL>>>(j);
        topk_kernel<<<N_ROWS / 8, 256>>>(target, idxp, j);
    }
    entropy_kernel<<<256, 256>>>();
    final_kernel<<<1, 256>>>(out);
}

// round 11
// speedup vs baseline: 2.1033x; 1.0160x over previous
#include <cuda_runtime.h>
#include <cuda_bf16.h>
#include <cstdint>
#include <math.h>

#define N_ROWS 4096
#define DIMS   128
#define NJ     4
#define TOPK   16

// smem map (bytes): 6 x 32KB bf16 tiles = 192KB
#define SM_AHI  0
#define SM_ALO  32768
#define SM_BHI0 65536
#define SM_BLO0 98304
#define SM_BHI1 131072
#define SM_BLO1 163840
#define SM_TOTAL 196608

// ---------------- device scratch (static, allocation-free) ----------------
__device__ __nv_bfloat16 g_fhi[N_ROWS * DIMS];
__device__ __nv_bfloat16 g_flo[N_ROWS * DIMS];
__device__ __nv_bfloat16 g_nhi[(size_t)NJ * N_ROWS * DIMS];
__device__ __nv_bfloat16 g_nlo[(size_t)NJ * N_ROWS * DIMS];
__device__ float g_sims[(size_t)NJ * N_ROWS * N_ROWS];   // 256 MB
__device__ float g_topbuf[N_ROWS * NJ * TOPK];
__device__ float g_part[256];

// ---------------- PTX helpers (base-arch portable: no tcgen05) ----------------
__device__ __forceinline__ uint32_t smem_u32(const void* p) {
    uint32_t a;
    asm("{ .reg .u64 t; cvta.to.shared.u64 t, %1; cvt.u32.u64 %0, t; }" : "=r"(a) : "l"(p));
    return a;
}
__device__ __forceinline__ void ldsm4(uint32_t* r, uint32_t a) {
    asm volatile("ldmatrix.sync.aligned.m8n8.x4.shared.b16 {%0,%1,%2,%3}, [%4];"
                 : "=r"(r[0]), "=r"(r[1]), "=r"(r[2]), "=r"(r[3]) : "r"(a));
}
// non-volatile: lets ptxas interleave MMAs among the pipelined LDSMs
__device__ __forceinline__ void mma16816(float* c, const uint32_t* a,
                                         uint32_t b0, uint32_t b1) {
    asm("mma.sync.aligned.m16n8k16.row.col.f32.bf16.bf16.f32 "
        "{%0,%1,%2,%3}, {%4,%5,%6,%7}, {%8,%9}, {%0,%1,%2,%3};"
        : "+f"(c[0]), "+f"(c[1]), "+f"(c[2]), "+f"(c[3])
        : "r"(a[0]), "r"(a[1]), "r"(a[2]), "r"(a[3]), "r"(b0), "r"(b1));
}

// Byte offset of (row, col) in a 128x128 bf16 tile stored as 8-row x 128B
// blocked atoms with SW128 XOR swizzle. col must be a multiple of 8.
__device__ __forceinline__ uint32_t toff(int row, int col) {
    return (uint32_t)(((row >> 3) + (col >> 6) * 16) * 1024 + (row & 7) * 128 +
                      ((((col >> 3) & 7) ^ (row & 7)) * 16));
}

// Stage a 128x128 bf16 tile (row-major in gmem) into swizzled smem via cp.async.
__device__ __forceinline__ void stage_async(uint32_t sdst,
                                            const __nv_bfloat16* __restrict__ g,
                                            int t) {
#pragma unroll
    for (int i = 0; i < 8; i++) {
        int c = t + 256 * i;              // 0..2047 16B chunks
        int row = c >> 4, kch = c & 15;
        uint32_t dst = sdst + toff(row, kch * 8);
        const void* src = g + row * DIMS + kch * 8;
        asm volatile("cp.async.cg.shared.global [%0], [%1], 16;" :: "r"(dst), "l"(src));
    }
}

// ---------------- kernel 0: normalize + bf16 hi/lo split ----------------
__global__ void convert_kernel(const float* __restrict__ feat,
                               const float* __restrict__ negs) {
    int gw = (blockIdx.x * blockDim.x + threadIdx.x) >> 5;
    int lane = threadIdx.x & 31;
    if (gw >= N_ROWS + NJ * N_ROWS) return;
    const float* src;
    __nv_bfloat16 *dh, *dl;
    if (gw < N_ROWS) {
        src = feat + (size_t)gw * DIMS;
        dh = g_fhi + (size_t)gw * DIMS;
        dl = g_flo + (size_t)gw * DIMS;
    } else {
        int r = gw - N_ROWS;
        src = negs + (size_t)r * DIMS;
        dh = g_nhi + (size_t)r * DIMS;
        dl = g_nlo + (size_t)r * DIMS;
    }
    float4 v = ((const float4*)src)[lane];
    float s = v.x * v.x + v.y * v.y + v.z * v.z + v.w * v.w;
#pragma unroll
    for (int off = 16; off; off >>= 1) s += __shfl_xor_sync(0xffffffffu, s, off);
    float rinv = 1.0f / fmaxf(sqrtf(s), 1e-12f);
    float x[4] = {v.x * rinv, v.y * rinv, v.z * rinv, v.w * rinv};
    __nv_bfloat16 h[4], l[4];
#pragma unroll
    for (int e = 0; e < 4; e++) {
        h[e] = __float2bfloat16(x[e]);
        l[e] = __float2bfloat16(x[e] - __bfloat162float(h[e]));
    }
    __nv_bfloat162* dh2 = (__nv_bfloat162*)(dh + 4 * lane);
    __nv_bfloat162* dl2 = (__nv_bfloat162*)(dl + 4 * lane);
    dh2[0] = __nv_bfloat162{h[0], h[1]};
    dh2[1] = __nv_bfloat162{h[2], h[3]};
    dl2[0] = __nv_bfloat162{l[0], l[1]};
    dl2[1] = __nv_bfloat162{l[2], l[3]};
}

// ---------------- kernel 1: HMMA GEMM (bf16 hi/lo 3-term) -> g_sims ----------------
// grid (32 queryTiles, 4 candChunks, NJ), block 256 (8 warps; warp 64q x 32c)
__global__ void __launch_bounds__(256, 1) gemm_kernel() {
    extern __shared__ char smem[];
    const int t = threadIdx.x, wid = t >> 5, lane = t & 31;
    const int n0 = blockIdx.x * 128;
    const int c0 = blockIdx.y * 1024;
    const int j  = blockIdx.z;
    const uint32_t sb = smem_u32(smem);

    const __nv_bfloat16* nh = g_nhi + ((size_t)j * N_ROWS + c0) * DIMS;
    const __nv_bfloat16* nl = g_nlo + ((size_t)j * N_ROWS + c0) * DIMS;
    float* simsj = g_sims + (size_t)j * N_ROWS * N_ROWS;

    // prologue: A (queries, fixed) + B tile 0
    stage_async(sb + SM_AHI, g_fhi + (size_t)n0 * DIMS, t);
    stage_async(sb + SM_ALO, g_flo + (size_t)n0 * DIMS, t);
    stage_async(sb + SM_BHI0, nh, t);
    stage_async(sb + SM_BLO0, nl, t);
    asm volatile("cp.async.commit_group;");

    const int qoff = (wid >> 2) * 64;
    const int coff = (wid & 3) * 32;
    const int a_r  = ((lane >> 3) & 1) * 8 + (lane & 7);
    const int a_c8 = (lane >> 4) * 8;

#pragma unroll 1
    for (int it = 0; it < 8; ++it) {
        const int cur = it & 1;
        if (it < 7) {
            stage_async(sb + (cur ? SM_BHI0 : SM_BHI1), nh + (size_t)(it + 1) * 128 * DIMS, t);
            stage_async(sb + (cur ? SM_BLO0 : SM_BLO1), nl + (size_t)(it + 1) * 128 * DIMS, t);
            asm volatile("cp.async.commit_group;");
            asm volatile("cp.async.wait_group 1;");
        } else {
            asm volatile("cp.async.wait_group 0;");
        }
        __syncthreads();

        const uint32_t bh_base = sb + (cur ? SM_BHI1 : SM_BHI0);
        const uint32_t bl_base = sb + (cur ? SM_BLO1 : SM_BLO0);

        float c[4][4][4];
#pragma unroll
        for (int mi = 0; mi < 4; mi++)
#pragma unroll
            for (int ni = 0; ni < 4; ni++)
#pragma unroll
                for (int e = 0; e < 4; e++) c[mi][ni][e] = 0.f;

        // register-double-buffered fragments (A: 4 mi-groups, B: 2 16c-groups)
        uint32_t ah[2][4][4], al[2][4][4], bh[2][2][4], bl[2][2][4];
#pragma unroll
        for (int mi = 0; mi < 4; mi++) {
            uint32_t off = toff(qoff + mi * 16 + a_r, a_c8);
            ldsm4(ah[0][mi], sb + SM_AHI + off);
            ldsm4(al[0][mi], sb + SM_ALO + off);
        }
#pragma unroll
        for (int g = 0; g < 2; g++) {
            uint32_t off = toff(coff + g * 16 + a_r, a_c8);
            ldsm4(bh[0][g], bh_base + off);
            ldsm4(bl[0][g], bl_base + off);
        }

#pragma unroll
        for (int kc = 0; kc < 8; ++kc) {
            const int s = kc & 1, nx = s ^ 1;
            if (kc < 7) {
#pragma unroll
                for (int mi = 0; mi < 4; mi++) {
                    uint32_t off = toff(qoff + mi * 16 + a_r, (kc + 1) * 16 + a_c8);
                    ldsm4(ah[nx][mi], sb + SM_AHI + off);
                    ldsm4(al[nx][mi], sb + SM_ALO + off);
                }
#pragma unroll
                for (int g = 0; g < 2; g++) {
                    uint32_t off = toff(coff + g * 16 + a_r, (kc + 1) * 16 + a_c8);
                    ldsm4(bh[nx][g], bh_base + off);
                    ldsm4(bl[nx][g], bl_base + off);
                }
            }
            // frag for ni: group g=ni>>1, sel=ni&1 -> {b[g][sel], b[g][2+sel]}
#pragma unroll
            for (int mi = 0; mi < 4; mi++)
#pragma unroll
                for (int ni = 0; ni < 4; ni++) {
                    const int g = ni >> 1, sl = ni & 1;
                    mma16816(c[mi][ni], ah[s][mi], bh[s][g][sl], bh[s][g][2 + sl]);
                    mma16816(c[mi][ni], ah[s][mi], bl[s][g][sl], bl[s][g][2 + sl]);
                    mma16816(c[mi][ni], al[s][mi], bh[s][g][sl], bh[s][g][2 + sl]);
                }
        }
        __syncthreads();   // smem reads done before next iter's cp.async overwrite

        // epilogue: C frag -> sims[q][cand] (coalesced STG.64)
        const int cand0 = c0 + it * 128 + coff;
#pragma unroll
        for (int mi = 0; mi < 4; mi++) {
            const int q = n0 + qoff + mi * 16 + (lane >> 2);
#pragma unroll
            for (int ni = 0; ni < 4; ni++) {
                const int cd = cand0 + ni * 8 + (lane & 3) * 2;
                *(float2*)&simsj[(size_t)q * N_ROWS + cd] =
                    make_float2(c[mi][ni][0], c[mi][ni][1]);
                *(float2*)&simsj[(size_t)(q + 8) * N_ROWS + cd] =
                    make_float2(c[mi][ni][2], c[mi][ni][3]);
            }
        }
    }
}

// ---------------- warp top-16 selection over a smem buffer ----------------
__device__ __forceinline__ float warp_select16(float* bw, int cnt, int lane,
                                               float* outp) {
    float x0 = (lane < cnt)      ? bw[lane]      : -INFINITY;
    float x1 = (lane + 32 < cnt) ? bw[lane + 32] : -INFINITY;
    float x2 = (lane + 64 < cnt) ? bw[lane + 64] : -INFINITY;
    float x3 = (lane + 96 < cnt) ? bw[lane + 96] : -INFINITY;
    float wm = -INFINITY;
#pragma unroll 1
    for (int k = 0; k < TOPK; k++) {
        float lm = fmaxf(fmaxf(x0, x1), fmaxf(x2, x3));
        wm = lm;
#pragma unroll
        for (int off = 16; off; off >>= 1)
            wm = fmaxf(wm, __shfl_xor_sync(0xffffffffu, wm, off));
        unsigned b = __ballot_sync(0xffffffffu, lm == wm);
        int leader = __ffs(b) - 1;
        if (lane == leader) {
            if      (x0 == wm) x0 = -INFINITY;
            else if (x1 == wm) x1 = -INFINITY;
            else if (x2 == wm) x2 = -INFINITY;
            else               x3 = -INFINITY;
        }
        if (lane == 0) {
            bw[k] = wm;
            if (outp) outp[k] = wm;
        }
    }
    return wm;
}

// ---------------- kernel 2: per-(row,j) top-16 over 4096 candidates ----------------
__global__ void __launch_bounds__(256)
topk_kernel(const int* __restrict__ target, const int* __restrict__ idxp) {
    __shared__ float buf[8][128];
    const int w    = threadIdx.x >> 5;
    const int lane = threadIdx.x & 31;
    const int row  = blockIdx.x * 8 + w;
    const int j    = blockIdx.y;
    const bool maskj = (j == *idxp);
    const int  myt   = target[row];
    const float* rowp = g_sims + ((size_t)j * N_ROWS + row) * N_ROWS;
    float* bw = buf[w];
    const unsigned lmask = (1u << lane) - 1u;

    float tau = -INFINITY;
    int   cnt = 0;

#pragma unroll 1
    for (int it = 0; it < N_ROWS / 128; ++it) {
        int c0 = it * 128 + lane * 4;
        float4 v = *(const float4*)(rowp + c0);
        if (maskj) {
            int4 tg = *(const int4*)(target + c0);
            if (tg.x == myt) v.x = -1e9f;
            if (tg.y == myt) v.y = -1e9f;
            if (tg.z == myt) v.z = -1e9f;
            if (tg.w == myt) v.w = -1e9f;
        }
        float vv[4] = {v.x, v.y, v.z, v.w};
#pragma unroll
        for (int e = 0; e < 4; e++) {
            bool p = vv[e] > tau;
            unsigned m = __ballot_sync(0xffffffffu, p);
            if (m) {
                if (p) bw[cnt + __popc(m & lmask)] = vv[e];
                cnt += __popc(m);
                __syncwarp();
                if (cnt > 96) {
                    tau = warp_select16(bw, cnt, lane, nullptr);
                    cnt = TOPK;
                    __syncwarp();
                }
            }
        }
    }
    float* outp = g_topbuf + ((size_t)row * NJ + j) * TOPK;
    warp_select16(bw, cnt, lane, outp);
}

// ---------------- kernel 3: entropy + decay, fine-grained (one (n,k) per thread) ----------------
__global__ void entropy_kernel() {
    __shared__ float red[256];
    const int id = blockIdx.x * 256 + threadIdx.x;   // 0..65535
    const int n = id >> 4, k = id & 15;
    const float* tb = g_topbuf + (size_t)n * (NJ * TOPK);

    float wsum = 0.f, w = 1.f;
#pragma unroll
    for (int i = 0; i < TOPK; i++) { wsum += w; w *= 0.95f; }
    float wk = 1.f;
    for (int i = 0; i < 16; i++) wk = (i < k) ? wk * 0.95f : wk;

    float l0 = tb[0 * TOPK + k] * 100.0f;
    float l1 = tb[1 * TOPK + k] * 100.0f;
    float l2 = tb[2 * TOPK + k] * 100.0f;
    float l3 = tb[3 * TOPK + k] * 100.0f;
    float m = fmaxf(fmaxf(l0, l1), fmaxf(l2, l3));
    float e0 = expf(l0 - m), e1 = expf(l1 - m), e2 = expf(l2 - m), e3 = expf(l3 - m);
    float s  = e0 + e1 + e2 + e3;
    float t1 = e0 * (l0 - m) + e1 * (l1 - m) + e2 * (l2 - m) + e3 * (l3 - m);
    float ent = t1 / s - logf(s);
    float acc = ent * wk / wsum;

    red[threadIdx.x] = acc;
    __syncthreads();
    for (int off = 128; off; off >>= 1) {
        if (threadIdx.x < off) red[threadIdx.x] += red[threadIdx.x + off];
        __syncthreads();
    }
    if (threadIdx.x == 0) g_part[blockIdx.x] = red[0];
}

// ---------------- kernel 4: deterministic final reduction (256 partials) ----------------
__global__ void final_kernel(float* out) {
    __shared__ float red[256];
    red[threadIdx.x] = g_part[threadIdx.x];
    __syncthreads();
    for (int off = 128; off; off >>= 1) {
        if (threadIdx.x < off) red[threadIdx.x] += red[threadIdx.x + off];
        __syncthreads();
    }
    if (threadIdx.x == 0) out[0] = red[0] / (float)N_ROWS + logf((float)NJ);
}

// ---------------- launch ----------------
extern "C" void kernel_launch(void* const* d_in, const int* in_sizes, int n_in,
                              void* d_out, int out_size) {
    const float* feat   = (const float*)d_in[0];
    const int*   target = (const int*)d_in[1];
    const float* negs   = (const float*)d_in[2];
    const int*   idxp   = (const int*)d_in[3];
    float*       out    = (float*)d_out;

    cudaFuncSetAttribute(gemm_kernel,
                         cudaFuncAttributeMaxDynamicSharedMemorySize, SM_TOTAL);

    convert_kernel<<<(N_ROWS + NJ * N_ROWS) / 8, 256>>>(feat, negs);
    gemm_kernel<<<dim3(32, 4, NJ), 256, SM_TOTAL>>>();
    topk_kernel<<<dim3(N_ROWS / 8, NJ), 256>>>(target, idxp);
    entropy_kernel<<<256, 256>>>();
    final_kernel<<<1, 256>>>(out);
}

// round 12
// speedup vs baseline: 2.1438x; 1.0192x over previous
#include <cuda_runtime.h>
#include <cuda_bf16.h>
#include <cstdint>
#include <math.h>

#define N_ROWS 4096
#define DIMS   128
#define NJ     4
#define TOPK   16

// smem map (bytes): 6 x 32KB bf16 tiles = 192KB
#define SM_AHI  0
#define SM_ALO  32768
#define SM_BHI0 65536
#define SM_BLO0 98304
#define SM_BHI1 131072
#define SM_BLO1 163840
#define SM_TOTAL 196608

// ---------------- device scratch (static, allocation-free) ----------------
__device__ __nv_bfloat16 g_fhi[N_ROWS * DIMS];
__device__ __nv_bfloat16 g_flo[N_ROWS * DIMS];
__device__ __nv_bfloat16 g_nhi[(size_t)NJ * N_ROWS * DIMS];
__device__ __nv_bfloat16 g_nlo[(size_t)NJ * N_ROWS * DIMS];
__device__ float g_sims[(size_t)NJ * N_ROWS * N_ROWS];   // 256 MB
__device__ float g_topbuf[N_ROWS * NJ * TOPK];
__device__ float g_part[256];

// ---------------- PTX helpers (base-arch portable: no tcgen05) ----------------
__device__ __forceinline__ uint32_t smem_u32(const void* p) {
    uint32_t a;
    asm("{ .reg .u64 t; cvta.to.shared.u64 t, %1; cvt.u32.u64 %0, t; }" : "=r"(a) : "l"(p));
    return a;
}
__device__ __forceinline__ void ldsm4(uint32_t* r, uint32_t a) {
    asm volatile("ldmatrix.sync.aligned.m8n8.x4.shared.b16 {%0,%1,%2,%3}, [%4];"
                 : "=r"(r[0]), "=r"(r[1]), "=r"(r[2]), "=r"(r[3]) : "r"(a));
}
__device__ __forceinline__ void mma16816(float* c, const uint32_t* a,
                                         uint32_t b0, uint32_t b1) {
    asm("mma.sync.aligned.m16n8k16.row.col.f32.bf16.bf16.f32 "
        "{%0,%1,%2,%3}, {%4,%5,%6,%7}, {%8,%9}, {%0,%1,%2,%3};"
        : "+f"(c[0]), "+f"(c[1]), "+f"(c[2]), "+f"(c[3])
        : "r"(a[0]), "r"(a[1]), "r"(a[2]), "r"(a[3]), "r"(b0), "r"(b1));
}

// Byte offset of (row, col) in a 128x128 bf16 tile stored as 8-row x 128B
// blocked atoms with SW128 XOR swizzle. col must be a multiple of 8.
__device__ __forceinline__ uint32_t toff(int row, int col) {
    return (uint32_t)(((row >> 3) + (col >> 6) * 16) * 1024 + (row & 7) * 128 +
                      ((((col >> 3) & 7) ^ (row & 7)) * 16));
}

// Stage a 128x128 bf16 tile (row-major in gmem) into swizzled smem via cp.async.
// 512-thread version: 2048 16B chunks, 4 per thread.
__device__ __forceinline__ void stage_async(uint32_t sdst,
                                            const __nv_bfloat16* __restrict__ g,
                                            int t) {
#pragma unroll
    for (int i = 0; i < 4; i++) {
        int c = t + 512 * i;              // 0..2047 16B chunks
        int row = c >> 4, kch = c & 15;
        uint32_t dst = sdst + toff(row, kch * 8);
        const void* src = g + row * DIMS + kch * 8;
        asm volatile("cp.async.cg.shared.global [%0], [%1], 16;" :: "r"(dst), "l"(src));
    }
}

// ---------------- kernel 0: normalize + bf16 hi/lo split ----------------
__global__ void convert_kernel(const float* __restrict__ feat,
                               const float* __restrict__ negs) {
    int gw = (blockIdx.x * blockDim.x + threadIdx.x) >> 5;
    int lane = threadIdx.x & 31;
    if (gw >= N_ROWS + NJ * N_ROWS) return;
    const float* src;
    __nv_bfloat16 *dh, *dl;
    if (gw < N_ROWS) {
        src = feat + (size_t)gw * DIMS;
        dh = g_fhi + (size_t)gw * DIMS;
        dl = g_flo + (size_t)gw * DIMS;
    } else {
        int r = gw - N_ROWS;
        src = negs + (size_t)r * DIMS;
        dh = g_nhi + (size_t)r * DIMS;
        dl = g_nlo + (size_t)r * DIMS;
    }
    float4 v = ((const float4*)src)[lane];
    float s = v.x * v.x + v.y * v.y + v.z * v.z + v.w * v.w;
#pragma unroll
    for (int off = 16; off; off >>= 1) s += __shfl_xor_sync(0xffffffffu, s, off);
    float rinv = 1.0f / fmaxf(sqrtf(s), 1e-12f);
    float x[4] = {v.x * rinv, v.y * rinv, v.z * rinv, v.w * rinv};
    __nv_bfloat16 h[4], l[4];
#pragma unroll
    for (int e = 0; e < 4; e++) {
        h[e] = __float2bfloat16(x[e]);
        l[e] = __float2bfloat16(x[e] - __bfloat162float(h[e]));
    }
    __nv_bfloat162* dh2 = (__nv_bfloat162*)(dh + 4 * lane);
    __nv_bfloat162* dl2 = (__nv_bfloat162*)(dl + 4 * lane);
    dh2[0] = __nv_bfloat162{h[0], h[1]};
    dh2[1] = __nv_bfloat162{h[2], h[3]};
    dl2[0] = __nv_bfloat162{l[0], l[1]};
    dl2[1] = __nv_bfloat162{l[2], l[3]};
}

// ---------------- kernel 1: HMMA GEMM (bf16 hi/lo 3-term) -> g_sims ----------------
// grid (32 queryTiles, 4 candChunks, NJ), block 512
// 16 warps in a 4x4 grid of 32q x 32c warp tiles (4 warps per SMSP).
__global__ void __launch_bounds__(512, 1) gemm_kernel() {
    extern __shared__ char smem[];
    const int t = threadIdx.x, wid = t >> 5, lane = t & 31;
    const int n0 = blockIdx.x * 128;
    const int c0 = blockIdx.y * 1024;
    const int j  = blockIdx.z;
    const uint32_t sb = smem_u32(smem);

    const __nv_bfloat16* nh = g_nhi + ((size_t)j * N_ROWS + c0) * DIMS;
    const __nv_bfloat16* nl = g_nlo + ((size_t)j * N_ROWS + c0) * DIMS;
    float* simsj = g_sims + (size_t)j * N_ROWS * N_ROWS;

    // prologue: A (queries, fixed) + B tile 0
    stage_async(sb + SM_AHI, g_fhi + (size_t)n0 * DIMS, t);
    stage_async(sb + SM_ALO, g_flo + (size_t)n0 * DIMS, t);
    stage_async(sb + SM_BHI0, nh, t);
    stage_async(sb + SM_BLO0, nl, t);
    asm volatile("cp.async.commit_group;");

    const int qoff = (wid >> 2) * 32;
    const int coff = (wid & 3) * 32;
    const int a_r  = ((lane >> 3) & 1) * 8 + (lane & 7);
    const int a_c8 = (lane >> 4) * 8;

#pragma unroll 1
    for (int it = 0; it < 8; ++it) {
        const int cur = it & 1;
        if (it < 7) {
            stage_async(sb + (cur ? SM_BHI0 : SM_BHI1), nh + (size_t)(it + 1) * 128 * DIMS, t);
            stage_async(sb + (cur ? SM_BLO0 : SM_BLO1), nl + (size_t)(it + 1) * 128 * DIMS, t);
            asm volatile("cp.async.commit_group;");
            asm volatile("cp.async.wait_group 1;");
        } else {
            asm volatile("cp.async.wait_group 0;");
        }
        __syncthreads();

        const uint32_t bh_base = sb + (cur ? SM_BHI1 : SM_BHI0);
        const uint32_t bl_base = sb + (cur ? SM_BLO1 : SM_BLO0);

        float c[2][4][4];
#pragma unroll
        for (int mi = 0; mi < 2; mi++)
#pragma unroll
            for (int ni = 0; ni < 4; ni++)
#pragma unroll
                for (int e = 0; e < 4; e++) c[mi][ni][e] = 0.f;

#pragma unroll
        for (int kc = 0; kc < 8; ++kc) {
            uint32_t ah[2][4], al[2][4], bh[2][4], bl[2][4];
#pragma unroll
            for (int mi = 0; mi < 2; mi++) {
                uint32_t off = toff(qoff + mi * 16 + a_r, kc * 16 + a_c8);
                ldsm4(ah[mi], sb + SM_AHI + off);
                ldsm4(al[mi], sb + SM_ALO + off);
            }
#pragma unroll
            for (int g = 0; g < 2; g++) {
                uint32_t off = toff(coff + g * 16 + a_r, kc * 16 + a_c8);
                ldsm4(bh[g], bh_base + off);
                ldsm4(bl[g], bl_base + off);
            }
            // frag for ni: group g=ni>>1, sel=ni&1 -> {b[g][sl], b[g][2+sl]}
#pragma unroll
            for (int mi = 0; mi < 2; mi++)
#pragma unroll
                for (int ni = 0; ni < 4; ni++) {
                    const int g = ni >> 1, sl = ni & 1;
                    mma16816(c[mi][ni], ah[mi], bh[g][sl], bh[g][2 + sl]);
                    mma16816(c[mi][ni], ah[mi], bl[g][sl], bl[g][2 + sl]);
                    mma16816(c[mi][ni], al[mi], bh[g][sl], bh[g][2 + sl]);
                }
        }
        __syncthreads();   // smem reads done before next iter's cp.async overwrite

        // epilogue: C frag -> sims[q][cand] (coalesced STG.64)
        const int cand0 = c0 + it * 128 + coff;
#pragma unroll
        for (int mi = 0; mi < 2; mi++) {
            const int q = n0 + qoff + mi * 16 + (lane >> 2);
#pragma unroll
            for (int ni = 0; ni < 4; ni++) {
                const int cd = cand0 + ni * 8 + (lane & 3) * 2;
                *(float2*)&simsj[(size_t)q * N_ROWS + cd] =
                    make_float2(c[mi][ni][0], c[mi][ni][1]);
                *(float2*)&simsj[(size_t)(q + 8) * N_ROWS + cd] =
                    make_float2(c[mi][ni][2], c[mi][ni][3]);
            }
        }
    }
}

// ---------------- warp top-16 selection over a smem buffer ----------------
__device__ __forceinline__ float warp_select16(float* bw, int cnt, int lane,
                                               float* outp) {
    float x0 = (lane < cnt)      ? bw[lane]      : -INFINITY;
    float x1 = (lane + 32 < cnt) ? bw[lane + 32] : -INFINITY;
    float x2 = (lane + 64 < cnt) ? bw[lane + 64] : -INFINITY;
    float x3 = (lane + 96 < cnt) ? bw[lane + 96] : -INFINITY;
    float wm = -INFINITY;
#pragma unroll 1
    for (int k = 0; k < TOPK; k++) {
        float lm = fmaxf(fmaxf(x0, x1), fmaxf(x2, x3));
        wm = lm;
#pragma unroll
        for (int off = 16; off; off >>= 1)
            wm = fmaxf(wm, __shfl_xor_sync(0xffffffffu, wm, off));
        unsigned b = __ballot_sync(0xffffffffu, lm == wm);
        int leader = __ffs(b) - 1;
        if (lane == leader) {
            if      (x0 == wm) x0 = -INFINITY;
            else if (x1 == wm) x1 = -INFINITY;
            else if (x2 == wm) x2 = -INFINITY;
            else               x3 = -INFINITY;
        }
        if (lane == 0) {
            bw[k] = wm;
            if (outp) outp[k] = wm;
        }
    }
    return wm;
}

// ---------------- kernel 2: per-(row,j) top-16 over 4096 candidates ----------------
__global__ void __launch_bounds__(256)
topk_kernel(const int* __restrict__ target, const int* __restrict__ idxp) {
    __shared__ float buf[8][128];
    const int w    = threadIdx.x >> 5;
    const int lane = threadIdx.x & 31;
    const int row  = blockIdx.x * 8 + w;
    const int j    = blockIdx.y;
    const bool maskj = (j == *idxp);
    const int  myt   = target[row];
    const float* rowp = g_sims + ((size_t)j * N_ROWS + row) * N_ROWS;
    float* bw = buf[w];
    const unsigned lmask = (1u << lane) - 1u;

    float tau = -INFINITY;
    int   cnt = 0;

#pragma unroll 1
    for (int it = 0; it < N_ROWS / 128; ++it) {
        int c0 = it * 128 + lane * 4;
        float4 v = *(const float4*)(rowp + c0);
        if (maskj) {
            int4 tg = *(const int4*)(target + c0);
            if (tg.x == myt) v.x = -1e9f;
            if (tg.y == myt) v.y = -1e9f;
            if (tg.z == myt) v.z = -1e9f;
            if (tg.w == myt) v.w = -1e9f;
        }
        float vv[4] = {v.x, v.y, v.z, v.w};
#pragma unroll
        for (int e = 0; e < 4; e++) {
            bool p = vv[e] > tau;
            unsigned m = __ballot_sync(0xffffffffu, p);
            if (m) {
                if (p) bw[cnt + __popc(m & lmask)] = vv[e];
                cnt += __popc(m);
                __syncwarp();
                if (cnt > 96) {
                    tau = warp_select16(bw, cnt, lane, nullptr);
                    cnt = TOPK;
                    __syncwarp();
                }
            }
        }
    }
    float* outp = g_topbuf + ((size_t)row * NJ + j) * TOPK;
    warp_select16(bw, cnt, lane, outp);
}

// ---------------- kernel 3: entropy + decay, fine-grained (one (n,k) per thread) ----------------
__global__ void entropy_kernel() {
    __shared__ float red[256];
    const int id = blockIdx.x * 256 + threadIdx.x;   // 0..65535
    const int n = id >> 4, k = id & 15;
    const float* tb = g_topbuf + (size_t)n * (NJ * TOPK);

    float wsum = 0.f, w = 1.f;
#pragma unroll
    for (int i = 0; i < TOPK; i++) { wsum += w; w *= 0.95f; }
    float wk = 1.f;
    for (int i = 0; i < 16; i++) wk = (i < k) ? wk * 0.95f : wk;

    float l0 = tb[0 * TOPK + k] * 100.0f;
    float l1 = tb[1 * TOPK + k] * 100.0f;
    float l2 = tb[2 * TOPK + k] * 100.0f;
    float l3 = tb[3 * TOPK + k] * 100.0f;
    float m = fmaxf(fmaxf(l0, l1), fmaxf(l2, l3));
    float e0 = expf(l0 - m), e1 = expf(l1 - m), e2 = expf(l2 - m), e3 = expf(l3 - m);
    float s  = e0 + e1 + e2 + e3;
    float t1 = e0 * (l0 - m) + e1 * (l1 - m) + e2 * (l2 - m) + e3 * (l3 - m);
    float ent = t1 / s - logf(s);
    float acc = ent * wk / wsum;

    red[threadIdx.x] = acc;
    __syncthreads();
    for (int off = 128; off; off >>= 1) {
        if (threadIdx.x < off) red[threadIdx.x] += red[threadIdx.x + off];
        __syncthreads();
    }
    if (threadIdx.x == 0) g_part[blockIdx.x] = red[0];
}

// ---------------- kernel 4: deterministic final reduction (256 partials) ----------------
__global__ void final_kernel(float* out) {
    __shared__ float red[256];
    red[threadIdx.x] = g_part[threadIdx.x];
    __syncthreads();
    for (int off = 128; off; off >>= 1) {
        if (threadIdx.x < off) red[threadIdx.x] += red[threadIdx.x + off];
        __syncthreads();
    }
    if (threadIdx.x == 0) out[0] = red[0] / (float)N_ROWS + logf((float)NJ);
}

// ---------------- launch ----------------
extern "C" void kernel_launch(void* const* d_in, const int* in_sizes, int n_in,
                              void* d_out, int out_size) {
    const float* feat   = (const float*)d_in[0];
    const int*   target = (const int*)d_in[1];
    const float* negs   = (const float*)d_in[2];
    const int*   idxp   = (const int*)d_in[3];
    float*       out    = (float*)d_out;

    cudaFuncSetAttribute(gemm_kernel,
                         cudaFuncAttributeMaxDynamicSharedMemorySize, SM_TOTAL);

    convert_kernel<<<(N_ROWS + NJ * N_ROWS) / 8, 256>>>(feat, negs);
    gemm_kernel<<<dim3(32, 4, NJ), 512, SM_TOTAL>>>();
    topk_kernel<<<dim3(N_ROWS / 8, NJ), 256>>>(target, idxp);
    entropy_kernel<<<256, 256>>>();
    final_kernel<<<1, 256>>>(out);
}

// round 13
// speedup vs baseline: 2.5746x; 1.2010x over previous
#include <cuda_runtime.h>
#include <cuda_fp16.h>
#include <cstdint>
#include <math.h>

#define N_ROWS 4096
#define DIMS   128
#define NJ     4
#define TOPK   16

// smem map (bytes): A-hi (32KB) + double-buffered B hi/lo (4 x 32KB) = 160KB
#define SM_AHI  0
#define SM_BHI0 32768
#define SM_BLO0 65536
#define SM_BHI1 98304
#define SM_BLO1 131072
#define SM_TOTAL 163840

// ---------------- device scratch (static, allocation-free) ----------------
__device__ __half g_fhi[N_ROWS * DIMS];
__device__ __half g_nhi[(size_t)NJ * N_ROWS * DIMS];
__device__ __half g_nlo[(size_t)NJ * N_ROWS * DIMS];
__device__ float g_sims[(size_t)NJ * N_ROWS * N_ROWS];   // 256 MB
__device__ float g_topbuf[N_ROWS * NJ * TOPK];
__device__ float g_part[256];

// ---------------- PTX helpers (base-arch portable: no tcgen05) ----------------
__device__ __forceinline__ uint32_t smem_u32(const void* p) {
    uint32_t a;
    asm("{ .reg .u64 t; cvta.to.shared.u64 t, %1; cvt.u32.u64 %0, t; }" : "=r"(a) : "l"(p));
    return a;
}
__device__ __forceinline__ void ldsm4(uint32_t* r, uint32_t a) {
    asm volatile("ldmatrix.sync.aligned.m8n8.x4.shared.b16 {%0,%1,%2,%3}, [%4];"
                 : "=r"(r[0]), "=r"(r[1]), "=r"(r[2]), "=r"(r[3]) : "r"(a));
}
__device__ __forceinline__ void mma16816(float* c, const uint32_t* a,
                                         uint32_t b0, uint32_t b1) {
    asm("mma.sync.aligned.m16n8k16.row.col.f32.f16.f16.f32 "
        "{%0,%1,%2,%3}, {%4,%5,%6,%7}, {%8,%9}, {%0,%1,%2,%3};"
        : "+f"(c[0]), "+f"(c[1]), "+f"(c[2]), "+f"(c[3])
        : "r"(a[0]), "r"(a[1]), "r"(a[2]), "r"(a[3]), "r"(b0), "r"(b1));
}

// Byte offset of (row, col) in a 128x128 fp16 tile stored as 8-row x 128B
// blocked atoms with SW128 XOR swizzle. col must be a multiple of 8.
__device__ __forceinline__ uint32_t toff(int row, int col) {
    return (uint32_t)(((row >> 3) + (col >> 6) * 16) * 1024 + (row & 7) * 128 +
                      ((((col >> 3) & 7) ^ (row & 7)) * 16));
}

// Stage a 128x128 fp16 tile (row-major in gmem) into swizzled smem via cp.async.
// 512-thread version: 2048 16B chunks, 4 per thread.
__device__ __forceinline__ void stage_async(uint32_t sdst,
                                            const __half* __restrict__ g,
                                            int t) {
#pragma unroll
    for (int i = 0; i < 4; i++) {
        int c = t + 512 * i;              // 0..2047 16B chunks
        int row = c >> 4, kch = c & 15;
        uint32_t dst = sdst + toff(row, kch * 8);
        const void* src = g + row * DIMS + kch * 8;
        asm volatile("cp.async.cg.shared.global [%0], [%1], 16;" :: "r"(dst), "l"(src));
    }
}

// ---------------- kernel 0: normalize + fp16 (hi[, lo]) split ----------------
__global__ void convert_kernel(const float* __restrict__ feat,
                               const float* __restrict__ negs) {
    int gw = (blockIdx.x * blockDim.x + threadIdx.x) >> 5;
    int lane = threadIdx.x & 31;
    if (gw >= N_ROWS + NJ * N_ROWS) return;
    const float* src;
    __half *dh, *dl;
    bool want_lo;
    if (gw < N_ROWS) {
        src = feat + (size_t)gw * DIMS;
        dh = g_fhi + (size_t)gw * DIMS;
        dl = nullptr;  want_lo = false;
    } else {
        int r = gw - N_ROWS;
        src = negs + (size_t)r * DIMS;
        dh = g_nhi + (size_t)r * DIMS;
        dl = g_nlo + (size_t)r * DIMS;
        want_lo = true;
    }
    float4 v = ((const float4*)src)[lane];
    float s = v.x * v.x + v.y * v.y + v.z * v.z + v.w * v.w;
#pragma unroll
    for (int off = 16; off; off >>= 1) s += __shfl_xor_sync(0xffffffffu, s, off);
    float rinv = 1.0f / fmaxf(sqrtf(s), 1e-12f);
    float x[4] = {v.x * rinv, v.y * rinv, v.z * rinv, v.w * rinv};
    __half h[4], l[4];
#pragma unroll
    for (int e = 0; e < 4; e++) {
        h[e] = __float2half(x[e]);
        l[e] = __float2half(x[e] - __half2float(h[e]));
    }
    __half2* dh2 = (__half2*)(dh + 4 * lane);
    dh2[0] = __half2{h[0], h[1]};
    dh2[1] = __half2{h[2], h[3]};
    if (want_lo) {
        __half2* dl2 = (__half2*)(dl + 4 * lane);
        dl2[0] = __half2{l[0], l[1]};
        dl2[1] = __half2{l[2], l[3]};
    }
}

// ---------------- kernel 1: HMMA GEMM (fp16 2-term) -> g_sims ----------------
// grid (32 queryTiles, NJ), block 512 (16 warps; 4x4 grid of 32q x 32c tiles)
// Each CTA: 128 queries x all 4096 candidates (32 iterations), A staged once.
__global__ void __launch_bounds__(512, 1) gemm_kernel() {
    extern __shared__ char smem[];
    const int t = threadIdx.x, wid = t >> 5, lane = t & 31;
    const int n0 = blockIdx.x * 128;
    const int j  = blockIdx.y;
    const uint32_t sb = smem_u32(smem);

    const __half* nh = g_nhi + (size_t)j * N_ROWS * DIMS;
    const __half* nl = g_nlo + (size_t)j * N_ROWS * DIMS;
    float* simsj = g_sims + (size_t)j * N_ROWS * N_ROWS;

    // prologue: A-hi (queries, staged once) + B tile 0
    stage_async(sb + SM_AHI, g_fhi + (size_t)n0 * DIMS, t);
    stage_async(sb + SM_BHI0, nh, t);
    stage_async(sb + SM_BLO0, nl, t);
    asm volatile("cp.async.commit_group;");

    const int qoff = (wid >> 2) * 32;
    const int coff = (wid & 3) * 32;
    const int a_r  = ((lane >> 3) & 1) * 8 + (lane & 7);
    const int a_c8 = (lane >> 4) * 8;

#pragma unroll 1
    for (int it = 0; it < 32; ++it) {
        const int cur = it & 1;
        if (it < 31) {
            stage_async(sb + (cur ? SM_BHI0 : SM_BHI1), nh + (size_t)(it + 1) * 128 * DIMS, t);
            stage_async(sb + (cur ? SM_BLO0 : SM_BLO1), nl + (size_t)(it + 1) * 128 * DIMS, t);
            asm volatile("cp.async.commit_group;");
            asm volatile("cp.async.wait_group 1;");
        } else {
            asm volatile("cp.async.wait_group 0;");
        }
        __syncthreads();

        const uint32_t bh_base = sb + (cur ? SM_BHI1 : SM_BHI0);
        const uint32_t bl_base = sb + (cur ? SM_BLO1 : SM_BLO0);

        float c[2][4][4];
#pragma unroll
        for (int mi = 0; mi < 2; mi++)
#pragma unroll
            for (int ni = 0; ni < 4; ni++)
#pragma unroll
                for (int e = 0; e < 4; e++) c[mi][ni][e] = 0.f;

#pragma unroll
        for (int kc = 0; kc < 8; ++kc) {
            uint32_t ah[2][4], bh[2][4], bl[2][4];
#pragma unroll
            for (int mi = 0; mi < 2; mi++) {
                uint32_t off = toff(qoff + mi * 16 + a_r, kc * 16 + a_c8);
                ldsm4(ah[mi], sb + SM_AHI + off);
            }
#pragma unroll
            for (int g = 0; g < 2; g++) {
                uint32_t off = toff(coff + g * 16 + a_r, kc * 16 + a_c8);
                ldsm4(bh[g], bh_base + off);
                ldsm4(bl[g], bl_base + off);
            }
            // frag for ni: group g=ni>>1, sel=ni&1 -> {b[g][sl], b[g][2+sl]}
#pragma unroll
            for (int mi = 0; mi < 2; mi++)
#pragma unroll
                for (int ni = 0; ni < 4; ni++) {
                    const int g = ni >> 1, sl = ni & 1;
                    mma16816(c[mi][ni], ah[mi], bh[g][sl], bh[g][2 + sl]);
                    mma16816(c[mi][ni], ah[mi], bl[g][sl], bl[g][2 + sl]);
                }
        }
        __syncthreads();   // smem reads done before next iter's cp.async overwrite

        // epilogue: C frag -> sims[q][cand] (coalesced STG.64)
        const int cand0 = it * 128 + coff;
#pragma unroll
        for (int mi = 0; mi < 2; mi++) {
            const int q = n0 + qoff + mi * 16 + (lane >> 2);
#pragma unroll
            for (int ni = 0; ni < 4; ni++) {
                const int cd = cand0 + ni * 8 + (lane & 3) * 2;
                *(float2*)&simsj[(size_t)q * N_ROWS + cd] =
                    make_float2(c[mi][ni][0], c[mi][ni][1]);
                *(float2*)&simsj[(size_t)(q + 8) * N_ROWS + cd] =
                    make_float2(c[mi][ni][2], c[mi][ni][3]);
            }
        }
    }
}

// ---------------- warp top-16 selection over a smem buffer ----------------
__device__ __forceinline__ float warp_select16(float* bw, int cnt, int lane,
                                               float* outp) {
    float x0 = (lane < cnt)      ? bw[lane]      : -INFINITY;
    float x1 = (lane + 32 < cnt) ? bw[lane + 32] : -INFINITY;
    float x2 = (lane + 64 < cnt) ? bw[lane + 64] : -INFINITY;
    float x3 = (lane + 96 < cnt) ? bw[lane + 96] : -INFINITY;
    float wm = -INFINITY;
#pragma unroll 1
    for (int k = 0; k < TOPK; k++) {
        float lm = fmaxf(fmaxf(x0, x1), fmaxf(x2, x3));
        wm = lm;
#pragma unroll
        for (int off = 16; off; off >>= 1)
            wm = fmaxf(wm, __shfl_xor_sync(0xffffffffu, wm, off));
        unsigned b = __ballot_sync(0xffffffffu, lm == wm);
        int leader = __ffs(b) - 1;
        if (lane == leader) {
            if      (x0 == wm) x0 = -INFINITY;
            else if (x1 == wm) x1 = -INFINITY;
            else if (x2 == wm) x2 = -INFINITY;
            else               x3 = -INFINITY;
        }
        if (lane == 0) {
            bw[k] = wm;
            if (outp) outp[k] = wm;
        }
    }
    return wm;
}

// ---------------- kernel 2: per-(row,j) top-16 over 4096 candidates ----------------
__global__ void __launch_bounds__(256)
topk_kernel(const int* __restrict__ target, const int* __restrict__ idxp) {
    __shared__ float buf[8][128];
    const int w    = threadIdx.x >> 5;
    const int lane = threadIdx.x & 31;
    const int row  = blockIdx.x * 8 + w;
    const int j    = blockIdx.y;
    const bool maskj = (j == *idxp);
    const int  myt   = target[row];
    const float* rowp = g_sims + ((size_t)j * N_ROWS + row) * N_ROWS;
    float* bw = buf[w];
    const unsigned lmask = (1u << lane) - 1u;

    float tau = -INFINITY;
    int   cnt = 0;

#pragma unroll 1
    for (int it = 0; it < N_ROWS / 128; ++it) {
        int c0 = it * 128 + lane * 4;
        float4 v = *(const float4*)(rowp + c0);
        if (maskj) {
            int4 tg = *(const int4*)(target + c0);
            if (tg.x == myt) v.x = -1e9f;
            if (tg.y == myt) v.y = -1e9f;
            if (tg.z == myt) v.z = -1e9f;
            if (tg.w == myt) v.w = -1e9f;
        }
        float vv[4] = {v.x, v.y, v.z, v.w};
#pragma unroll
        for (int e = 0; e < 4; e++) {
            bool p = vv[e] > tau;
            unsigned m = __ballot_sync(0xffffffffu, p);
            if (m) {
                if (p) bw[cnt + __popc(m & lmask)] = vv[e];
                cnt += __popc(m);
                __syncwarp();
                if (cnt > 96) {
                    tau = warp_select16(bw, cnt, lane, nullptr);
                    cnt = TOPK;
                    __syncwarp();
                }
            }
        }
    }
    float* outp = g_topbuf + ((size_t)row * NJ + j) * TOPK;
    warp_select16(bw, cnt, lane, outp);
}

// ---------------- kernel 3: entropy + decay, fine-grained (one (n,k) per thread) ----------------
__global__ void entropy_kernel() {
    __shared__ float red[256];
    const int id = blockIdx.x * 256 + threadIdx.x;   // 0..65535
    const int n = id >> 4, k = id & 15;
    const float* tb = g_topbuf + (size_t)n * (NJ * TOPK);

    float wsum = 0.f, w = 1.f;
#pragma unroll
    for (int i = 0; i < TOPK; i++) { wsum += w; w *= 0.95f; }
    float wk = 1.f;
    for (int i = 0; i < 16; i++) wk = (i < k) ? wk * 0.95f : wk;

    float l0 = tb[0 * TOPK + k] * 100.0f;
    float l1 = tb[1 * TOPK + k] * 100.0f;
    float l2 = tb[2 * TOPK + k] * 100.0f;
    float l3 = tb[3 * TOPK + k] * 100.0f;
    float m = fmaxf(fmaxf(l0, l1), fmaxf(l2, l3));
    float e0 = expf(l0 - m), e1 = expf(l1 - m), e2 = expf(l2 - m), e3 = expf(l3 - m);
    float s  = e0 + e1 + e2 + e3;
    float t1 = e0 * (l0 - m) + e1 * (l1 - m) + e2 * (l2 - m) + e3 * (l3 - m);
    float ent = t1 / s - logf(s);
    float acc = ent * wk / wsum;

    red[threadIdx.x] = acc;
    __syncthreads();
    for (int off = 128; off; off >>= 1) {
        if (threadIdx.x < off) red[threadIdx.x] += red[threadIdx.x + off];
        __syncthreads();
    }
    if (threadIdx.x == 0) g_part[blockIdx.x] = red[0];
}

// ---------------- kernel 4: deterministic final reduction (256 partials) ----------------
__global__ void final_kernel(float* out) {
    __shared__ float red[256];
    red[threadIdx.x] = g_part[threadIdx.x];
    __syncthreads();
    for (int off = 128; off; off >>= 1) {
        if (threadIdx.x < off) red[threadIdx.x] += red[threadIdx.x + off];
        __syncthreads();
    }
    if (threadIdx.x == 0) out[0] = red[0] / (float)N_ROWS + logf((float)NJ);
}

// ---------------- launch ----------------
extern "C" void kernel_launch(void* const* d_in, const int* in_sizes, int n_in,
                              void* d_out, int out_size) {
    const float* feat   = (const float*)d_in[0];
    const int*   target = (const int*)d_in[1];
    const float* negs   = (const float*)d_in[2];
    const int*   idxp   = (const int*)d_in[3];
    float*       out    = (float*)d_out;

    cudaFuncSetAttribute(gemm_kernel,
                         cudaFuncAttributeMaxDynamicSharedMemorySize, SM_TOTAL);

    convert_kernel<<<(N_ROWS + NJ * N_ROWS) / 8, 256>>>(feat, negs);
    gemm_kernel<<<dim3(32, NJ), 512, SM_TOTAL>>>();
    topk_kernel<<<dim3(N_ROWS / 8, NJ), 256>>>(target, idxp);
    entropy_kernel<<<256, 256>>>();
    final_kernel<<<1, 256>>>(out);
}

// round 14
// speedup vs baseline: 3.2999x; 1.2817x over previous
#include <cuda_runtime.h>
#include <cuda_fp16.h>
#include <cstdint>
#include <math.h>

#define N_ROWS 4096
#define DIMS   128
#define NJ     4
#define TOPK   16

// smem map (bytes): A (32KB) + double-buffered B (2 x 32KB) = 96KB
#define SM_AHI  0
#define SM_B0   32768
#define SM_B1   65536
#define SM_TOTAL 98304

// ---------------- device scratch (static, allocation-free) ----------------
__device__ __half g_fhi[N_ROWS * DIMS];
__device__ __half g_nhi[(size_t)NJ * N_ROWS * DIMS];
__device__ __half g_sims[(size_t)NJ * N_ROWS * N_ROWS];   // 128 MB fp16
__device__ float g_topbuf[N_ROWS * NJ * TOPK];
__device__ float g_part[256];

// ---------------- PTX helpers (base-arch portable: no tcgen05) ----------------
__device__ __forceinline__ uint32_t smem_u32(const void* p) {
    uint32_t a;
    asm("{ .reg .u64 t; cvta.to.shared.u64 t, %1; cvt.u32.u64 %0, t; }" : "=r"(a) : "l"(p));
    return a;
}
__device__ __forceinline__ void ldsm4(uint32_t* r, uint32_t a) {
    asm volatile("ldmatrix.sync.aligned.m8n8.x4.shared.b16 {%0,%1,%2,%3}, [%4];"
                 : "=r"(r[0]), "=r"(r[1]), "=r"(r[2]), "=r"(r[3]) : "r"(a));
}
__device__ __forceinline__ void mma16816(float* c, const uint32_t* a,
                                         uint32_t b0, uint32_t b1) {
    asm("mma.sync.aligned.m16n8k16.row.col.f32.f16.f16.f32 "
        "{%0,%1,%2,%3}, {%4,%5,%6,%7}, {%8,%9}, {%0,%1,%2,%3};"
        : "+f"(c[0]), "+f"(c[1]), "+f"(c[2]), "+f"(c[3])
        : "r"(a[0]), "r"(a[1]), "r"(a[2]), "r"(a[3]), "r"(b0), "r"(b1));
}

// Byte offset of (row, col) in a 128x128 fp16 tile stored as 8-row x 128B
// blocked atoms with SW128 XOR swizzle. col must be a multiple of 8.
__device__ __forceinline__ uint32_t toff(int row, int col) {
    return (uint32_t)(((row >> 3) + (col >> 6) * 16) * 1024 + (row & 7) * 128 +
                      ((((col >> 3) & 7) ^ (row & 7)) * 16));
}

// Stage a 128x128 fp16 tile (row-major in gmem) into swizzled smem via cp.async.
// 512-thread version: 2048 16B chunks, 4 per thread.
__device__ __forceinline__ void stage_async(uint32_t sdst,
                                            const __half* __restrict__ g,
                                            int t) {
#pragma unroll
    for (int i = 0; i < 4; i++) {
        int c = t + 512 * i;              // 0..2047 16B chunks
        int row = c >> 4, kch = c & 15;
        uint32_t dst = sdst + toff(row, kch * 8);
        const void* src = g + row * DIMS + kch * 8;
        asm volatile("cp.async.cg.shared.global [%0], [%1], 16;" :: "r"(dst), "l"(src));
    }
}

// ---------------- kernel 0: normalize + fp16 convert ----------------
__global__ void convert_kernel(const float* __restrict__ feat,
                               const float* __restrict__ negs) {
    int gw = (blockIdx.x * blockDim.x + threadIdx.x) >> 5;
    int lane = threadIdx.x & 31;
    if (gw >= N_ROWS + NJ * N_ROWS) return;
    const float* src;
    __half* dh;
    if (gw < N_ROWS) {
        src = feat + (size_t)gw * DIMS;
        dh = g_fhi + (size_t)gw * DIMS;
    } else {
        int r = gw - N_ROWS;
        src = negs + (size_t)r * DIMS;
        dh = g_nhi + (size_t)r * DIMS;
    }
    float4 v = ((const float4*)src)[lane];
    float s = v.x * v.x + v.y * v.y + v.z * v.z + v.w * v.w;
#pragma unroll
    for (int off = 16; off; off >>= 1) s += __shfl_xor_sync(0xffffffffu, s, off);
    float rinv = 1.0f / fmaxf(sqrtf(s), 1e-12f);
    __half2* dh2 = (__half2*)(dh + 4 * lane);
    dh2[0] = __floats2half2_rn(v.x * rinv, v.y * rinv);
    dh2[1] = __floats2half2_rn(v.z * rinv, v.w * rinv);
}

// ---------------- kernel 1: HMMA GEMM (pure fp16) -> g_sims (fp16) ----------------
// grid (32 queryTiles, NJ), block 512 (16 warps; 4x4 grid of 32q x 32c tiles)
// Each CTA: 128 queries x all 4096 candidates (32 iterations), A staged once.
__global__ void __launch_bounds__(512, 1) gemm_kernel() {
    extern __shared__ char smem[];
    const int t = threadIdx.x, wid = t >> 5, lane = t & 31;
    const int n0 = blockIdx.x * 128;
    const int j  = blockIdx.y;
    const uint32_t sb = smem_u32(smem);

    const __half* nh = g_nhi + (size_t)j * N_ROWS * DIMS;
    __half* simsj = g_sims + (size_t)j * N_ROWS * N_ROWS;

    // prologue: A (queries, staged once) + B tile 0
    stage_async(sb + SM_AHI, g_fhi + (size_t)n0 * DIMS, t);
    stage_async(sb + SM_B0, nh, t);
    asm volatile("cp.async.commit_group;");

    const int qoff = (wid >> 2) * 32;
    const int coff = (wid & 3) * 32;
    const int a_r  = ((lane >> 3) & 1) * 8 + (lane & 7);
    const int a_c8 = (lane >> 4) * 8;

#pragma unroll 1
    for (int it = 0; it < 32; ++it) {
        const int cur = it & 1;
        if (it < 31) {
            stage_async(sb + (cur ? SM_B0 : SM_B1), nh + (size_t)(it + 1) * 128 * DIMS, t);
            asm volatile("cp.async.commit_group;");
            asm volatile("cp.async.wait_group 1;");
        } else {
            asm volatile("cp.async.wait_group 0;");
        }
        __syncthreads();

        const uint32_t b_base = sb + (cur ? SM_B1 : SM_B0);

        float c[2][4][4];
#pragma unroll
        for (int mi = 0; mi < 2; mi++)
#pragma unroll
            for (int ni = 0; ni < 4; ni++)
#pragma unroll
                for (int e = 0; e < 4; e++) c[mi][ni][e] = 0.f;

#pragma unroll
        for (int kc = 0; kc < 8; ++kc) {
            uint32_t ah[2][4], bh[2][4];
#pragma unroll
            for (int mi = 0; mi < 2; mi++) {
                uint32_t off = toff(qoff + mi * 16 + a_r, kc * 16 + a_c8);
                ldsm4(ah[mi], sb + SM_AHI + off);
            }
#pragma unroll
            for (int g = 0; g < 2; g++) {
                uint32_t off = toff(coff + g * 16 + a_r, kc * 16 + a_c8);
                ldsm4(bh[g], b_base + off);
            }
            // frag for ni: group g=ni>>1, sel=ni&1 -> {b[g][sl], b[g][2+sl]}
#pragma unroll
            for (int mi = 0; mi < 2; mi++)
#pragma unroll
                for (int ni = 0; ni < 4; ni++) {
                    const int g = ni >> 1, sl = ni & 1;
                    mma16816(c[mi][ni], ah[mi], bh[g][sl], bh[g][2 + sl]);
                }
        }
        __syncthreads();   // smem reads done before next iter's cp.async overwrite

        // epilogue: C frag -> sims[q][cand] as fp16 (coalesced STG.32 half2)
        const int cand0 = it * 128 + coff;
#pragma unroll
        for (int mi = 0; mi < 2; mi++) {
            const int q = n0 + qoff + mi * 16 + (lane >> 2);
#pragma unroll
            for (int ni = 0; ni < 4; ni++) {
                const int cd = cand0 + ni * 8 + (lane & 3) * 2;
                *(__half2*)&simsj[(size_t)q * N_ROWS + cd] =
                    __floats2half2_rn(c[mi][ni][0], c[mi][ni][1]);
                *(__half2*)&simsj[(size_t)(q + 8) * N_ROWS + cd] =
                    __floats2half2_rn(c[mi][ni][2], c[mi][ni][3]);
            }
        }
    }
}

// ---------------- warp top-16 selection over a smem buffer ----------------
__device__ __forceinline__ float warp_select16(float* bw, int cnt, int lane,
                                               float* outp) {
    float x0 = (lane < cnt)      ? bw[lane]      : -INFINITY;
    float x1 = (lane + 32 < cnt) ? bw[lane + 32] : -INFINITY;
    float x2 = (lane + 64 < cnt) ? bw[lane + 64] : -INFINITY;
    float x3 = (lane + 96 < cnt) ? bw[lane + 96] : -INFINITY;
    float wm = -INFINITY;
#pragma unroll 1
    for (int k = 0; k < TOPK; k++) {
        float lm = fmaxf(fmaxf(x0, x1), fmaxf(x2, x3));
        wm = lm;
#pragma unroll
        for (int off = 16; off; off >>= 1)
            wm = fmaxf(wm, __shfl_xor_sync(0xffffffffu, wm, off));
        unsigned b = __ballot_sync(0xffffffffu, lm == wm);
        int leader = __ffs(b) - 1;
        if (lane == leader) {
            if      (x0 == wm) x0 = -INFINITY;
            else if (x1 == wm) x1 = -INFINITY;
            else if (x2 == wm) x2 = -INFINITY;
            else               x3 = -INFINITY;
        }
        if (lane == 0) {
            bw[k] = wm;
            if (outp) outp[k] = wm;
        }
    }
    return wm;
}

// ---------------- kernel 2: per-(row,j) top-16 over 4096 fp16 candidates ----------------
__global__ void __launch_bounds__(256)
topk_kernel(const int* __restrict__ target, const int* __restrict__ idxp) {
    __shared__ float buf[8][128];
    const int w    = threadIdx.x >> 5;
    const int lane = threadIdx.x & 31;
    const int row  = blockIdx.x * 8 + w;
    const int j    = blockIdx.y;
    const bool maskj = (j == *idxp);
    const int  myt   = target[row];
    const __half* rowp = g_sims + ((size_t)j * N_ROWS + row) * N_ROWS;
    float* bw = buf[w];
    const unsigned lmask = (1u << lane) - 1u;

    float tau = -INFINITY;
    int   cnt = 0;

#pragma unroll 1
    for (int it = 0; it < N_ROWS / 128; ++it) {
        int c0 = it * 128 + lane * 4;
        const __half2* hp = (const __half2*)(rowp + c0);
        __half2 h01 = hp[0], h23 = hp[1];
        float4 v = make_float4(__low2float(h01), __high2float(h01),
                               __low2float(h23), __high2float(h23));
        if (maskj) {
            int4 tg = *(const int4*)(target + c0);
            if (tg.x == myt) v.x = -1e9f;
            if (tg.y == myt) v.y = -1e9f;
            if (tg.z == myt) v.z = -1e9f;
            if (tg.w == myt) v.w = -1e9f;
        }
        float vv[4] = {v.x, v.y, v.z, v.w};
#pragma unroll
        for (int e = 0; e < 4; e++) {
            bool p = vv[e] > tau;
            unsigned m = __ballot_sync(0xffffffffu, p);
            if (m) {
                if (p) bw[cnt + __popc(m & lmask)] = vv[e];
                cnt += __popc(m);
                __syncwarp();
                if (cnt > 96) {
                    tau = warp_select16(bw, cnt, lane, nullptr);
                    cnt = TOPK;
                    __syncwarp();
                }
            }
        }
    }
    float* outp = g_topbuf + ((size_t)row * NJ + j) * TOPK;
    warp_select16(bw, cnt, lane, outp);
}

// ---------------- kernel 3: entropy + decay, fine-grained (one (n,k) per thread) ----------------
__global__ void entropy_kernel() {
    __shared__ float red[256];
    const int id = blockIdx.x * 256 + threadIdx.x;   // 0..65535
    const int n = id >> 4, k = id & 15;
    const float* tb = g_topbuf + (size_t)n * (NJ * TOPK);

    float wsum = 0.f, w = 1.f;
#pragma unroll
    for (int i = 0; i < TOPK; i++) { wsum += w; w *= 0.95f; }
    float wk = 1.f;
    for (int i = 0; i < 16; i++) wk = (i < k) ? wk * 0.95f : wk;

    float l0 = tb[0 * TOPK + k] * 100.0f;
    float l1 = tb[1 * TOPK + k] * 100.0f;
    float l2 = tb[2 * TOPK + k] * 100.0f;
    float l3 = tb[3 * TOPK + k] * 100.0f;
    float m = fmaxf(fmaxf(l0, l1), fmaxf(l2, l3));
    float e0 = expf(l0 - m), e1 = expf(l1 - m), e2 = expf(l2 - m), e3 = expf(l3 - m);
    float s  = e0 + e1 + e2 + e3;
    float t1 = e0 * (l0 - m) + e1 * (l1 - m) + e2 * (l2 - m) + e3 * (l3 - m);
    float ent = t1 / s - logf(s);
    float acc = ent * wk / wsum;

    red[threadIdx.x] = acc;
    __syncthreads();
    for (int off = 128; off; off >>= 1) {
        if (threadIdx.x < off) red[threadIdx.x] += red[threadIdx.x + off];
        __syncthreads();
    }
    if (threadIdx.x == 0) g_part[blockIdx.x] = red[0];
}

// ---------------- kernel 4: deterministic final reduction (256 partials) ----------------
__global__ void final_kernel(float* out) {
    __shared__ float red[256];
    red[threadIdx.x] = g_part[threadIdx.x];
    __syncthreads();
    for (int off = 128; off; off >>= 1) {
        if (threadIdx.x < off) red[threadIdx.x] += red[threadIdx.x + off];
        __syncthreads();
    }
    if (threadIdx.x == 0) out[0] = red[0] / (float)N_ROWS + logf((float)NJ);
}

// ---------------- launch ----------------
extern "C" void kernel_launch(void* const* d_in, const int* in_sizes, int n_in,
                              void* d_out, int out_size) {
    const float* feat   = (const float*)d_in[0];
    const int*   target = (const int*)d_in[1];
    const float* negs   = (const float*)d_in[2];
    const int*   idxp   = (const int*)d_in[3];
    float*       out    = (float*)d_out;

    cudaFuncSetAttribute(gemm_kernel,
                         cudaFuncAttributeMaxDynamicSharedMemorySize, SM_TOTAL);

    convert_kernel<<<(N_ROWS + NJ * N_ROWS) / 8, 256>>>(feat, negs);
    gemm_kernel<<<dim3(32, NJ), 512, SM_TOTAL>>>();
    topk_kernel<<<dim3(N_ROWS / 8, NJ), 256>>>(target, idxp);
    entropy_kernel<<<256, 256>>>();
    final_kernel<<<1, 256>>>(out);
}